// round 4
// baseline (speedup 1.0000x reference)
#include <cuda_runtime.h>
#include <math.h>

#define Bz   64
#define Lz   512
#define Dz   256
#define Vz   32000
#define Kz   6
#define Hz   4
#define HDz  64
#define FFNz 512

// -------- scratch (static device globals; no allocation) --------
__device__ float g_x  [Bz*Lz*Dz];
__device__ float g_h  [Bz*Lz*Dz];
__device__ float g_qkv[Bz*Lz*3*Dz];
__device__ float g_o  [Bz*Lz*Dz];
__device__ float g_ffn[Bz*Lz*FFNz];
__device__ float g_z  [Bz*Dz];
__device__ int   g_len[Bz];

// -------- reduction helpers --------
__device__ __forceinline__ float warpSum(float v) {
#pragma unroll
    for (int o = 16; o; o >>= 1) v += __shfl_xor_sync(0xffffffffu, v, o);
    return v;
}
__device__ __forceinline__ float warpMax(float v) {
#pragma unroll
    for (int o = 16; o; o >>= 1) v = fmaxf(v, __shfl_xor_sync(0xffffffffu, v, o));
    return v;
}
// 256-thread block sum; red must be float[8]; safe for repeated use.
__device__ __forceinline__ float blkSum256(float v, float* red) {
    int lane = threadIdx.x & 31, w = threadIdx.x >> 5;
    v = warpSum(v);
    __syncthreads();
    if (lane == 0) red[w] = v;
    __syncthreads();
    float s = 0.f;
#pragma unroll
    for (int i = 0; i < 8; i++) s += red[i];
    return s;
}

__device__ __forceinline__ float gelu_f(float x) {
    return 0.5f * x * (1.0f + erff(x * 0.70710678118654752f));
}

// -------- lengths from tokens (mask == tokens != 0, prefix) --------
__global__ void __launch_bounds__(256) lengths_kernel(const int* __restrict__ tokens) {
    __shared__ float red[8];
    int b = blockIdx.x, tid = threadIdx.x;
    float c = (tokens[b*Lz + tid] != 0 ? 1.f : 0.f) +
              (tokens[b*Lz + 256 + tid] != 0 ? 1.f : 0.f);
    float s = blkSum256(c, red);
    if (tid == 0) g_len[b] = (int)(s + 0.5f);
}

// -------- fused embedding + LN --------
__global__ void __launch_bounds__(256) embed_kernel(
    const int* __restrict__ tokens, const float* __restrict__ te,
    const float* __restrict__ pe, const float* __restrict__ g,
    const float* __restrict__ bb)
{
    __shared__ float red[8];
    int row = blockIdx.x;           // b*Lz + l
    int l = row & (Lz - 1);
    int d = threadIdx.x;
    int tok = tokens[row];
    float v = te[(size_t)tok*Dz + d] + pe[(size_t)l*Dz + d];
    float mu  = blkSum256(v, red) * (1.0f/256.0f);
    float dv  = v - mu;
    float var = blkSum256(dv*dv, red) * (1.0f/256.0f);
    g_x[(size_t)row*Dz + d] = dv * rsqrtf(var + 1e-5f) * g[d] + bb[d];
}

// -------- generic row LN --------
__global__ void __launch_bounds__(256) ln_kernel(
    const float* __restrict__ in, const float* __restrict__ g,
    const float* __restrict__ bb, float* __restrict__ out)
{
    __shared__ float red[8];
    size_t row = blockIdx.x;
    int d = threadIdx.x;
    float v = in[row*Dz + d];
    float mu  = blkSum256(v, red) * (1.0f/256.0f);
    float dv  = v - mu;
    float var = blkSum256(dv*dv, red) * (1.0f/256.0f);
    out[row*Dz + d] = dv * rsqrtf(var + 1e-5f) * g[d] + bb[d];
}

// -------- tiled NT SGEMM: C[M,N] = A[M,K] * B[N,K]^T + bias (+Res) (+GELU) --------
// BM=64, BN=128, BK=16, 256 threads, thread tile 4x8.
template<bool GELU, bool RES>
__global__ void __launch_bounds__(256) gemm_nt(
    const float* __restrict__ A, const float* __restrict__ B,
    const float* __restrict__ bias, const float* __restrict__ Res,
    float* __restrict__ C, int M, int N, int Kd)
{
    __shared__ __align__(16) float As[16][68];
    __shared__ __align__(16) float Bs[16][132];
    const int m0 = blockIdx.y * 64;
    const int n0 = blockIdx.x * 128;
    const int tid = threadIdx.x;
    const int tx = tid & 15, ty = tid >> 4;
    const float* Ag = A + (size_t)m0 * Kd;
    const float* Bg = B + (size_t)n0 * Kd;
    const int ar = tid >> 2, akv = (tid & 3) * 4;
    float acc[4][8] = {};

    for (int k0 = 0; k0 < Kd; k0 += 16) {
        float4 a4 = *reinterpret_cast<const float4*>(Ag + (size_t)ar*Kd + k0 + akv);
        As[akv+0][ar] = a4.x; As[akv+1][ar] = a4.y;
        As[akv+2][ar] = a4.z; As[akv+3][ar] = a4.w;
#pragma unroll
        for (int i = 0; i < 2; i++) {
            int idx = tid + i*256;
            int br = idx >> 2, bkv = (idx & 3) * 4;
            float4 b4 = *reinterpret_cast<const float4*>(Bg + (size_t)br*Kd + k0 + bkv);
            Bs[bkv+0][br] = b4.x; Bs[bkv+1][br] = b4.y;
            Bs[bkv+2][br] = b4.z; Bs[bkv+3][br] = b4.w;
        }
        __syncthreads();
#pragma unroll
        for (int k = 0; k < 16; k++) {
            float4 av = *reinterpret_cast<const float4*>(&As[k][ty*4]);
            float4 b0 = *reinterpret_cast<const float4*>(&Bs[k][tx*8]);
            float4 b1 = *reinterpret_cast<const float4*>(&Bs[k][tx*8+4]);
            const float* a  = reinterpret_cast<const float*>(&av);
            const float* p0 = reinterpret_cast<const float*>(&b0);
            const float* p1 = reinterpret_cast<const float*>(&b1);
#pragma unroll
            for (int i = 0; i < 4; i++) {
#pragma unroll
                for (int j = 0; j < 4; j++) acc[i][j]   = fmaf(a[i], p0[j], acc[i][j]);
#pragma unroll
                for (int j = 0; j < 4; j++) acc[i][4+j] = fmaf(a[i], p1[j], acc[i][4+j]);
            }
        }
        __syncthreads();
    }
#pragma unroll
    for (int i = 0; i < 4; i++) {
        int m = m0 + ty*4 + i;
#pragma unroll
        for (int j = 0; j < 8; j++) {
            int n = n0 + tx*8 + j;
            float v = acc[i][j] + bias[n];
            if (RES)  v += Res[(size_t)m*N + n];
            if (GELU) v = gelu_f(v);
            C[(size_t)m*N + n] = v;
        }
    }
}

// -------- attention: one block per (q-tile of 64 rows, head, batch) --------
#define ATTN_SMEM ((512 + 64 + 64) * 68 * 4)

__global__ void __launch_bounds__(256) attn_kernel(
    const float* __restrict__ qkv, float* __restrict__ o)
{
    extern __shared__ float sm[];
    float (*S )[68] = reinterpret_cast<float(*)[68]>(sm);            // [512][68], S[c][r]
    float (*Qs)[68] = reinterpret_cast<float(*)[68]>(sm + 512*68);   // [64][68],  Qs[d][r]
    float (*KV)[68] = reinterpret_cast<float(*)[68]>(sm + 576*68);   // [64][68]

    const int l0 = blockIdx.x * 64;
    const int h  = blockIdx.y;
    const int b  = blockIdx.z;
    const int tid = threadIdx.x;
    const int tx = tid & 15, ty = tid >> 4;
    const int lane = tid & 31, warp = tid >> 5;
    const float* base = qkv + (size_t)b * Lz * (3*Dz);

    // Q tile transposed into Qs[d][r], pre-scaled by 1/sqrt(HD)=0.125
#pragma unroll
    for (int i = 0; i < 4; i++) {
        int idx = tid + i*256;
        int r = idx >> 4, dv = (idx & 15) * 4;
        float4 v = *reinterpret_cast<const float4*>(
            base + (size_t)(l0 + r)*(3*Dz) + h*HDz + dv);
        Qs[dv+0][r] = v.x*0.125f; Qs[dv+1][r] = v.y*0.125f;
        Qs[dv+2][r] = v.z*0.125f; Qs[dv+3][r] = v.w*0.125f;
    }

    // S = Q K^T (streamed K tiles)
    for (int kt = 0; kt < 8; kt++) {
#pragma unroll
        for (int i = 0; i < 4; i++) {
            int idx = tid + i*256;
            int c = idx >> 4, dv = (idx & 15) * 4;
            float4 v = *reinterpret_cast<const float4*>(
                base + (size_t)(kt*64 + c)*(3*Dz) + Dz + h*HDz + dv);
            KV[dv+0][c] = v.x; KV[dv+1][c] = v.y;
            KV[dv+2][c] = v.z; KV[dv+3][c] = v.w;
        }
        __syncthreads();
        float acc[4][4] = {};
#pragma unroll 8
        for (int d = 0; d < 64; d++) {
            float4 av = *reinterpret_cast<const float4*>(&Qs[d][ty*4]);
            float4 bv = *reinterpret_cast<const float4*>(&KV[d][tx*4]);
            const float* a = reinterpret_cast<const float*>(&av);
            const float* bq = reinterpret_cast<const float*>(&bv);
#pragma unroll
            for (int i = 0; i < 4; i++)
#pragma unroll
                for (int j = 0; j < 4; j++)
                    acc[i][j] = fmaf(a[i], bq[j], acc[i][j]);
        }
#pragma unroll
        for (int j = 0; j < 4; j++)
#pragma unroll
            for (int i = 0; i < 4; i++)
                S[kt*64 + tx*4 + j][ty*4 + i] = acc[i][j];
        __syncthreads();
    }

    // masked softmax per q row (each warp owns 8 rows)
    const int len = g_len[b];
    for (int rr = 0; rr < 8; rr++) {
        int r = warp*8 + rr;
        float mx = -3.4e38f;
        for (int c = lane; c < 512; c += 32) {
            float v = (c < len) ? S[c][r] : -1e9f;
            mx = fmaxf(mx, v);
        }
        mx = warpMax(mx);
        float sum = 0.f;
        for (int c = lane; c < 512; c += 32) {
            float v = (c < len) ? S[c][r] : -1e9f;
            float p = __expf(v - mx);
            S[c][r] = p;
            sum += p;
        }
        sum = warpSum(sum);
        float inv = 1.0f / sum;
        for (int c = lane; c < 512; c += 32) S[c][r] *= inv;
    }
    __syncthreads();

    // O = A V (streamed V tiles)
    float oacc[4][4] = {};
    for (int kt = 0; kt < 8; kt++) {
#pragma unroll
        for (int i = 0; i < 4; i++) {
            int idx = tid + i*256;
            int c = idx >> 4, dv = (idx & 15) * 4;
            float4 v = *reinterpret_cast<const float4*>(
                base + (size_t)(kt*64 + c)*(3*Dz) + 2*Dz + h*HDz + dv);
            *reinterpret_cast<float4*>(&KV[c][dv]) = v;
        }
        __syncthreads();
#pragma unroll 8
        for (int c = 0; c < 64; c++) {
            float4 av = *reinterpret_cast<const float4*>(&S[kt*64 + c][ty*4]);
            float4 vv = *reinterpret_cast<const float4*>(&KV[c][tx*4]);
            const float* a = reinterpret_cast<const float*>(&av);
            const float* vp = reinterpret_cast<const float*>(&vv);
#pragma unroll
            for (int i = 0; i < 4; i++)
#pragma unroll
                for (int j = 0; j < 4; j++)
                    oacc[i][j] = fmaf(a[i], vp[j], oacc[i][j]);
        }
        __syncthreads();
    }
#pragma unroll
    for (int i = 0; i < 4; i++)
#pragma unroll
        for (int j = 0; j < 4; j++)
            o[((size_t)b*Lz + l0 + ty*4 + i)*Dz + h*HDz + tx*4 + j] = oacc[i][j];
}

// -------- final attention pooling --------
__global__ void __launch_bounds__(256) pool_kernel(const float* __restrict__ x) {
    __shared__ float q[256];
    __shared__ float sc[512];
    __shared__ float red[8];
    int b = blockIdx.x, tid = threadIdx.x;
    int lane = tid & 31, w = tid >> 5;
    int len = g_len[b];
    const float* xb = x + (size_t)b * Lz * Dz;
    q[tid] = xb[(size_t)(len - 1)*Dz + tid];
    __syncthreads();
    for (int l = w; l < Lz; l += 8) {
        float p = 0.f;
        const float* xr = xb + (size_t)l*Dz;
        for (int k = lane; k < Dz; k += 32) p += q[k]*xr[k];
        p = warpSum(p);
        if (lane == 0) sc[l] = (l < len) ? p : -60000.0f;
    }
    __syncthreads();
    float m1 = fmaxf(sc[tid], sc[tid + 256]);
    m1 = warpMax(m1);
    if (lane == 0) red[w] = m1;
    __syncthreads();
    float mx = -3.4e38f;
#pragma unroll
    for (int i = 0; i < 8; i++) mx = fmaxf(mx, red[i]);
    __syncthreads();
    float e0 = __expf(sc[tid] - mx), e1 = __expf(sc[tid + 256] - mx);
    sc[tid] = e0; sc[tid + 256] = e1;
    float s = blkSum256(e0 + e1, red);
    float inv = 1.0f / s;
    float acc = 0.f;
    for (int l = 0; l < Lz; l++) acc += sc[l] * xb[(size_t)l*Dz + tid];
    g_z[b*Dz + tid] = acc * inv;
}

// -------- host orchestration --------
extern "C" void kernel_launch(void* const* d_in, const int* in_sizes, int n_in,
                              void* d_out, int out_size)
{
    (void)in_sizes; (void)n_in; (void)out_size;
    const int*   tokens  = (const int*)  d_in[0];
    // d_in[1] = mask (unused; derived from tokens)
    const float* tok_emb = (const float*)d_in[2];
    const float* pos_emb = (const float*)d_in[3];
    const float* eg      = (const float*)d_in[4];
    const float* ebt     = (const float*)d_in[5];
    const float* ln1g    = (const float*)d_in[6];
    const float* ln1b    = (const float*)d_in[7];
    const float* Wqkv    = (const float*)d_in[8];
    const float* bqkv    = (const float*)d_in[9];
    const float* Wo      = (const float*)d_in[10];
    const float* bo      = (const float*)d_in[11];
    const float* ln2g    = (const float*)d_in[12];
    const float* ln2b    = (const float*)d_in[13];
    const float* W1      = (const float*)d_in[14];
    const float* b1      = (const float*)d_in[15];
    const float* W2      = (const float*)d_in[16];
    const float* b2      = (const float*)d_in[17];
    // d_in[18..21] = GRU params: dead code (m never affects output) — skipped
    const float* clsW    = (const float*)d_in[22];
    const float* clsb    = (const float*)d_in[23];
    float* out = (float*)d_out;

    float *px, *ph, *pqkv, *po, *pffn, *pz;
    cudaGetSymbolAddress((void**)&px,   g_x);
    cudaGetSymbolAddress((void**)&ph,   g_h);
    cudaGetSymbolAddress((void**)&pqkv, g_qkv);
    cudaGetSymbolAddress((void**)&po,   g_o);
    cudaGetSymbolAddress((void**)&pffn, g_ffn);
    cudaGetSymbolAddress((void**)&pz,   g_z);

    cudaFuncSetAttribute(attn_kernel,
        cudaFuncAttributeMaxDynamicSharedMemorySize, ATTN_SMEM);

    const int M = Bz * Lz;   // 32768

    lengths_kernel<<<Bz, 256>>>(tokens);
    embed_kernel<<<M, 256>>>(tokens, tok_emb, pos_emb, eg, ebt);

    for (int e = 0; e < Kz; e++) {
        ln_kernel<<<M, 256>>>(px, ln1g + e*Dz, ln1b + e*Dz, ph);
        gemm_nt<false,false><<<dim3(3*Dz/128, M/64), 256>>>(
            ph, Wqkv + (size_t)e*3*Dz*Dz, bqkv + (size_t)e*3*Dz, nullptr,
            pqkv, M, 3*Dz, Dz);
        attn_kernel<<<dim3(Lz/64, Hz, Bz), 256, ATTN_SMEM>>>(pqkv, po);
        gemm_nt<false,true><<<dim3(Dz/128, M/64), 256>>>(
            po, Wo + (size_t)e*Dz*Dz, bo + (size_t)e*Dz, px,
            px, M, Dz, Dz);
        ln_kernel<<<M, 256>>>(px, ln2g + e*Dz, ln2b + e*Dz, ph);
        gemm_nt<true,false><<<dim3(FFNz/128, M/64), 256>>>(
            ph, W1 + (size_t)e*FFNz*Dz, b1 + (size_t)e*FFNz, nullptr,
            pffn, M, FFNz, Dz);
        gemm_nt<false,true><<<dim3(Dz/128, M/64), 256>>>(
            pffn, W2 + (size_t)e*Dz*FFNz, b2 + (size_t)e*Dz, px,
            px, M, Dz, FFNz);
    }

    pool_kernel<<<Bz, 256>>>(px);
    gemm_nt<false,false><<<dim3(Vz/128, Bz/64), 256>>>(
        pz, clsW, clsb, nullptr, out, Bz, Vz, Dz);
}

// round 7
// speedup vs baseline: 1.6109x; 1.6109x over previous
#include <cuda_runtime.h>
#include <math.h>

#define Bz   64
#define Lz   512
#define Dz   256
#define Vz   32000
#define Kz   6
#define Hz   4
#define HDz  64
#define FFNz 512

// -------- scratch (static device globals; no allocation) --------
__device__ float g_x  [Bz*Lz*Dz];
__device__ float g_h  [Bz*Lz*Dz];
__device__ float g_qkv[Bz*Lz*3*Dz];
__device__ float g_o  [Bz*Lz*Dz];
__device__ float g_ffn[Bz*Lz*FFNz];
__device__ float g_z  [Bz*Dz];
__device__ int   g_len[Bz];

// -------- reduction helpers --------
__device__ __forceinline__ float warpSum(float v) {
#pragma unroll
    for (int o = 16; o; o >>= 1) v += __shfl_xor_sync(0xffffffffu, v, o);
    return v;
}
__device__ __forceinline__ float warpMax(float v) {
#pragma unroll
    for (int o = 16; o; o >>= 1) v = fmaxf(v, __shfl_xor_sync(0xffffffffu, v, o));
    return v;
}
__device__ __forceinline__ float blkSum256(float v, float* red) {
    int lane = threadIdx.x & 31, w = threadIdx.x >> 5;
    v = warpSum(v);
    __syncthreads();
    if (lane == 0) red[w] = v;
    __syncthreads();
    float s = 0.f;
#pragma unroll
    for (int i = 0; i < 8; i++) s += red[i];
    return s;
}

__device__ __forceinline__ float gelu_f(float x) {
    return 0.5f * x * (1.0f + erff(x * 0.70710678118654752f));
}

// -------- lengths from tokens (mask == tokens != 0, prefix) --------
__global__ void __launch_bounds__(256) lengths_kernel(const int* __restrict__ tokens) {
    __shared__ float red[8];
    int b = blockIdx.x, tid = threadIdx.x;
    float c = (tokens[b*Lz + tid] != 0 ? 1.f : 0.f) +
              (tokens[b*Lz + 256 + tid] != 0 ? 1.f : 0.f);
    float s = blkSum256(c, red);
    if (tid == 0) g_len[b] = (int)(s + 0.5f);
}

// -------- fused embedding + LN --------
__global__ void __launch_bounds__(256) embed_kernel(
    const int* __restrict__ tokens, const float* __restrict__ te,
    const float* __restrict__ pe, const float* __restrict__ g,
    const float* __restrict__ bb)
{
    __shared__ float red[8];
    int row = blockIdx.x;
    int l = row & (Lz - 1);
    int d = threadIdx.x;
    int tok = tokens[row];
    float v = te[(size_t)tok*Dz + d] + pe[(size_t)l*Dz + d];
    float mu  = blkSum256(v, red) * (1.0f/256.0f);
    float dv  = v - mu;
    float var = blkSum256(dv*dv, red) * (1.0f/256.0f);
    g_x[(size_t)row*Dz + d] = dv * rsqrtf(var + 1e-5f) * g[d] + bb[d];
}

// -------- generic row LN --------
__global__ void __launch_bounds__(256) ln_kernel(
    const float* __restrict__ in, const float* __restrict__ g,
    const float* __restrict__ bb, float* __restrict__ out)
{
    __shared__ float red[8];
    size_t row = blockIdx.x;
    int d = threadIdx.x;
    float v = in[row*Dz + d];
    float mu  = blkSum256(v, red) * (1.0f/256.0f);
    float dv  = v - mu;
    float var = blkSum256(dv*dv, red) * (1.0f/256.0f);
    out[row*Dz + d] = dv * rsqrtf(var + 1e-5f) * g[d] + bb[d];
}

// ==================== SGEMM v2: 128x128x16, 8x8 microtile, double-buffered ====
// C[M,N] = A[M,K] * B[N,K]^T + bias (+Res) (+GELU).  M%128==0, N%128==0, K%16==0.
template<bool GELU, bool RES>
__global__ void __launch_bounds__(256, 2) gemm_nt2(
    const float* __restrict__ A, const float* __restrict__ B,
    const float* __restrict__ bias, const float* __restrict__ Res,
    float* __restrict__ C, int M, int N, int Kd)
{
    __shared__ __align__(16) float As[2][16][132];
    __shared__ __align__(16) float Bs[2][16][132];
    const int m0 = blockIdx.y * 128;
    const int n0 = blockIdx.x * 128;
    const int tid = threadIdx.x;
    const int tx = tid & 15, ty = tid >> 4;
    const float* Ag = A + (size_t)m0 * Kd;
    const float* Bg = B + (size_t)n0 * Kd;

    const int r0 = tid >> 2,        kv0 = (tid & 3) * 4;        // load slot 0
    const int r1 = (tid + 256) >> 2, kv1 = kv0;                 // load slot 1

    float acc[8][8] = {};
    float4 pa0, pa1, pb0, pb1;

    // prologue: tile 0
    pa0 = *reinterpret_cast<const float4*>(Ag + (size_t)r0*Kd + kv0);
    pa1 = *reinterpret_cast<const float4*>(Ag + (size_t)r1*Kd + kv1);
    pb0 = *reinterpret_cast<const float4*>(Bg + (size_t)r0*Kd + kv0);
    pb1 = *reinterpret_cast<const float4*>(Bg + (size_t)r1*Kd + kv1);
    As[0][kv0+0][r0]=pa0.x; As[0][kv0+1][r0]=pa0.y; As[0][kv0+2][r0]=pa0.z; As[0][kv0+3][r0]=pa0.w;
    As[0][kv1+0][r1]=pa1.x; As[0][kv1+1][r1]=pa1.y; As[0][kv1+2][r1]=pa1.z; As[0][kv1+3][r1]=pa1.w;
    Bs[0][kv0+0][r0]=pb0.x; Bs[0][kv0+1][r0]=pb0.y; Bs[0][kv0+2][r0]=pb0.z; Bs[0][kv0+3][r0]=pb0.w;
    Bs[0][kv1+0][r1]=pb1.x; Bs[0][kv1+1][r1]=pb1.y; Bs[0][kv1+2][r1]=pb1.z; Bs[0][kv1+3][r1]=pb1.w;
    __syncthreads();

    const int nk = Kd >> 4;
    for (int t = 0; t < nk; t++) {
        const int cur = t & 1, nxt = cur ^ 1;
        if (t + 1 < nk) {
            int k0 = (t + 1) << 4;
            pa0 = *reinterpret_cast<const float4*>(Ag + (size_t)r0*Kd + k0 + kv0);
            pa1 = *reinterpret_cast<const float4*>(Ag + (size_t)r1*Kd + k0 + kv1);
            pb0 = *reinterpret_cast<const float4*>(Bg + (size_t)r0*Kd + k0 + kv0);
            pb1 = *reinterpret_cast<const float4*>(Bg + (size_t)r1*Kd + k0 + kv1);
        }
#pragma unroll
        for (int k = 0; k < 16; k++) {
            float a[8], b[8];
            *reinterpret_cast<float4*>(a)   = *reinterpret_cast<const float4*>(&As[cur][k][ty*8]);
            *reinterpret_cast<float4*>(a+4) = *reinterpret_cast<const float4*>(&As[cur][k][ty*8+4]);
            *reinterpret_cast<float4*>(b)   = *reinterpret_cast<const float4*>(&Bs[cur][k][tx*8]);
            *reinterpret_cast<float4*>(b+4) = *reinterpret_cast<const float4*>(&Bs[cur][k][tx*8+4]);
#pragma unroll
            for (int i = 0; i < 8; i++)
#pragma unroll
                for (int j = 0; j < 8; j++)
                    acc[i][j] = fmaf(a[i], b[j], acc[i][j]);
        }
        if (t + 1 < nk) {
            As[nxt][kv0+0][r0]=pa0.x; As[nxt][kv0+1][r0]=pa0.y; As[nxt][kv0+2][r0]=pa0.z; As[nxt][kv0+3][r0]=pa0.w;
            As[nxt][kv1+0][r1]=pa1.x; As[nxt][kv1+1][r1]=pa1.y; As[nxt][kv1+2][r1]=pa1.z; As[nxt][kv1+3][r1]=pa1.w;
            Bs[nxt][kv0+0][r0]=pb0.x; Bs[nxt][kv0+1][r0]=pb0.y; Bs[nxt][kv0+2][r0]=pb0.z; Bs[nxt][kv0+3][r0]=pb0.w;
            Bs[nxt][kv1+0][r1]=pb1.x; Bs[nxt][kv1+1][r1]=pb1.y; Bs[nxt][kv1+2][r1]=pb1.z; Bs[nxt][kv1+3][r1]=pb1.w;
            __syncthreads();
        }
    }

#pragma unroll
    for (int i = 0; i < 8; i++) {
        int m = m0 + ty*8 + i;
        int nb = n0 + tx*8;
        float v[8];
#pragma unroll
        for (int j = 0; j < 8; j++) {
            v[j] = acc[i][j] + bias[nb + j];
            if (RES)  v[j] += Res[(size_t)m*N + nb + j];
            if (GELU) v[j] = gelu_f(v[j]);
        }
        *reinterpret_cast<float4*>(&C[(size_t)m*N + nb])     = *reinterpret_cast<float4*>(v);
        *reinterpret_cast<float4*>(&C[(size_t)m*N + nb + 4]) = *reinterpret_cast<float4*>(v + 4);
    }
}

// -------- old SGEMM (kept for classifier: M=64 rows) --------
template<bool GELU, bool RES>
__global__ void __launch_bounds__(256) gemm_nt(
    const float* __restrict__ A, const float* __restrict__ B,
    const float* __restrict__ bias, const float* __restrict__ Res,
    float* __restrict__ C, int M, int N, int Kd)
{
    __shared__ __align__(16) float As[16][68];
    __shared__ __align__(16) float Bs[16][132];
    const int m0 = blockIdx.y * 64;
    const int n0 = blockIdx.x * 128;
    const int tid = threadIdx.x;
    const int tx = tid & 15, ty = tid >> 4;
    const float* Ag = A + (size_t)m0 * Kd;
    const float* Bg = B + (size_t)n0 * Kd;
    const int ar = tid >> 2, akv = (tid & 3) * 4;
    float acc[4][8] = {};

    for (int k0 = 0; k0 < Kd; k0 += 16) {
        float4 a4 = *reinterpret_cast<const float4*>(Ag + (size_t)ar*Kd + k0 + akv);
        As[akv+0][ar] = a4.x; As[akv+1][ar] = a4.y;
        As[akv+2][ar] = a4.z; As[akv+3][ar] = a4.w;
#pragma unroll
        for (int i = 0; i < 2; i++) {
            int idx = tid + i*256;
            int br = idx >> 2, bkv = (idx & 3) * 4;
            float4 b4 = *reinterpret_cast<const float4*>(Bg + (size_t)br*Kd + k0 + bkv);
            Bs[bkv+0][br] = b4.x; Bs[bkv+1][br] = b4.y;
            Bs[bkv+2][br] = b4.z; Bs[bkv+3][br] = b4.w;
        }
        __syncthreads();
#pragma unroll
        for (int k = 0; k < 16; k++) {
            float4 av = *reinterpret_cast<const float4*>(&As[k][ty*4]);
            float4 b0 = *reinterpret_cast<const float4*>(&Bs[k][tx*8]);
            float4 b1 = *reinterpret_cast<const float4*>(&Bs[k][tx*8+4]);
            const float* a  = reinterpret_cast<const float*>(&av);
            const float* p0 = reinterpret_cast<const float*>(&b0);
            const float* p1 = reinterpret_cast<const float*>(&b1);
#pragma unroll
            for (int i = 0; i < 4; i++) {
#pragma unroll
                for (int j = 0; j < 4; j++) acc[i][j]   = fmaf(a[i], p0[j], acc[i][j]);
#pragma unroll
                for (int j = 0; j < 4; j++) acc[i][4+j] = fmaf(a[i], p1[j], acc[i][4+j]);
            }
        }
        __syncthreads();
    }
#pragma unroll
    for (int i = 0; i < 4; i++) {
        int m = m0 + ty*4 + i;
#pragma unroll
        for (int j = 0; j < 8; j++) {
            int n = n0 + tx*8 + j;
            float v = acc[i][j] + bias[n];
            if (RES)  v += Res[(size_t)m*N + n];
            if (GELU) v = gelu_f(v);
            C[(size_t)m*N + n] = v;
        }
    }
}

// ==================== flash-style attention ====================
// One block per (64-row q tile, head, batch). Online softmax; S never hits smem
// in full — only a 64x64 P tile. smem = Qs + KV + Ps = 3 * 64*68*4 = 52,224 B.
#define ATTN2_SMEM (3 * 64 * 68 * 4)

__global__ void __launch_bounds__(256) attn2_kernel(
    const float* __restrict__ qkv, float* __restrict__ o)
{
    extern __shared__ float sm[];
    float (*Qs)[68] = reinterpret_cast<float(*)[68]>(sm);            // Qs[d][r]
    float (*KV)[68] = reinterpret_cast<float(*)[68]>(sm + 64*68);    // K: [d][c], V: [c][d]
    float (*Ps)[68] = reinterpret_cast<float(*)[68]>(sm + 2*64*68);  // Ps[c][r]

    const int l0 = blockIdx.x * 64;
    const int h  = blockIdx.y;
    const int b  = blockIdx.z;
    const int tid = threadIdx.x;
    const int tx = tid & 15, ty = tid >> 4;
    const float* base = qkv + (size_t)b * Lz * (3*Dz);
    const int len = g_len[b];

    // Q tile transposed into Qs[d][r], pre-scaled by 1/sqrt(HD)=0.125
#pragma unroll
    for (int i = 0; i < 4; i++) {
        int idx = tid + i*256;
        int r = idx >> 4, dv = (idx & 15) * 4;
        float4 v = *reinterpret_cast<const float4*>(
            base + (size_t)(l0 + r)*(3*Dz) + h*HDz + dv);
        Qs[dv+0][r] = v.x*0.125f; Qs[dv+1][r] = v.y*0.125f;
        Qs[dv+2][r] = v.z*0.125f; Qs[dv+3][r] = v.w*0.125f;
    }

    float mrow[4], lrow[4], oacc[4][4];
#pragma unroll
    for (int i = 0; i < 4; i++) {
        mrow[i] = -3.4e38f; lrow[i] = 0.f;
#pragma unroll
        for (int j = 0; j < 4; j++) oacc[i][j] = 0.f;
    }
    __syncthreads();

    for (int kt = 0; kt < 8; kt++) {
        const int cbase = kt * 64;
        // ---- K tile transposed into KV[d][c] ----
#pragma unroll
        for (int i = 0; i < 4; i++) {
            int idx = tid + i*256;
            int c = idx >> 4, dv = (idx & 15) * 4;
            float4 v = *reinterpret_cast<const float4*>(
                base + (size_t)(cbase + c)*(3*Dz) + Dz + h*HDz + dv);
            KV[dv+0][c] = v.x; KV[dv+1][c] = v.y;
            KV[dv+2][c] = v.z; KV[dv+3][c] = v.w;
        }
        __syncthreads();

        // ---- S tile in registers: s[i][j], row = ty*4+i, col = cbase+tx*4+j ----
        float s[4][4] = {};
#pragma unroll 8
        for (int d = 0; d < 64; d++) {
            float4 av = *reinterpret_cast<const float4*>(&Qs[d][ty*4]);
            float4 bv = *reinterpret_cast<const float4*>(&KV[d][tx*4]);
            const float* a = reinterpret_cast<const float*>(&av);
            const float* kq = reinterpret_cast<const float*>(&bv);
#pragma unroll
            for (int i = 0; i < 4; i++)
#pragma unroll
                for (int j = 0; j < 4; j++)
                    s[i][j] = fmaf(a[i], kq[j], s[i][j]);
        }

        // ---- masked row max over 16 lanes sharing each row ----
        float rmax[4];
#pragma unroll
        for (int i = 0; i < 4; i++) {
            float rm = -1e9f;
#pragma unroll
            for (int j = 0; j < 4; j++) {
                int c = cbase + tx*4 + j;
                rm = fmaxf(rm, (c < len) ? s[i][j] : -1e9f);
            }
#pragma unroll
            for (int off = 1; off < 16; off <<= 1)
                rm = fmaxf(rm, __shfl_xor_sync(0xffffffffu, rm, off));
            rmax[i] = rm;
        }

        // ---- online rescale + P ----
        float rsum[4];
#pragma unroll
        for (int i = 0; i < 4; i++) {
            float mn = fmaxf(mrow[i], rmax[i]);
            float corr = __expf(mrow[i] - mn);
            lrow[i] *= corr;
#pragma unroll
            for (int j = 0; j < 4; j++) oacc[i][j] *= corr;
            mrow[i] = mn;
            float rs = 0.f;
#pragma unroll
            for (int j = 0; j < 4; j++) {
                int c = cbase + tx*4 + j;
                float p = (c < len) ? __expf(s[i][j] - mn) : 0.f;
                s[i][j] = p;
                rs += p;
            }
#pragma unroll
            for (int off = 1; off < 16; off <<= 1)
                rs += __shfl_xor_sync(0xffffffffu, rs, off);
            rsum[i] = rs;
        }
#pragma unroll
        for (int i = 0; i < 4; i++) lrow[i] += rsum[i];

        // ---- P to smem (transposed: Ps[c][r]) ----
#pragma unroll
        for (int j = 0; j < 4; j++)
#pragma unroll
            for (int i = 0; i < 4; i++)
                Ps[tx*4 + j][ty*4 + i] = s[i][j];
        __syncthreads();   // P written; K reads of KV done -> safe to overwrite with V

        // ---- V tile into KV[c][d] ----
#pragma unroll
        for (int i = 0; i < 4; i++) {
            int idx = tid + i*256;
            int c = idx >> 4, dv = (idx & 15) * 4;
            float4 v = *reinterpret_cast<const float4*>(
                base + (size_t)(cbase + c)*(3*Dz) + 2*Dz + h*HDz + dv);
            *reinterpret_cast<float4*>(&KV[c][dv]) = v;
        }
        __syncthreads();

        // ---- O += P @ V ----
#pragma unroll 8
        for (int c = 0; c < 64; c++) {
            float4 av = *reinterpret_cast<const float4*>(&Ps[c][ty*4]);
            float4 vv = *reinterpret_cast<const float4*>(&KV[c][tx*4]);
            const float* a  = reinterpret_cast<const float*>(&av);
            const float* vp = reinterpret_cast<const float*>(&vv);
#pragma unroll
            for (int i = 0; i < 4; i++)
#pragma unroll
                for (int j = 0; j < 4; j++)
                    oacc[i][j] = fmaf(a[i], vp[j], oacc[i][j]);
        }
        __syncthreads();   // before next iteration overwrites KV / Ps
    }

#pragma unroll
    for (int i = 0; i < 4; i++) {
        float inv = 1.0f / lrow[i];
#pragma unroll
        for (int j = 0; j < 4; j++)
            o[((size_t)b*Lz + l0 + ty*4 + i)*Dz + h*HDz + tx*4 + j] = oacc[i][j] * inv;
    }
}

// -------- final attention pooling --------
__global__ void __launch_bounds__(256) pool_kernel(const float* __restrict__ x) {
    __shared__ float q[256];
    __shared__ float sc[512];
    __shared__ float red[8];
    int b = blockIdx.x, tid = threadIdx.x;
    int lane = tid & 31, w = tid >> 5;
    int len = g_len[b];
    const float* xb = x + (size_t)b * Lz * Dz;
    q[tid] = xb[(size_t)(len - 1)*Dz + tid];
    __syncthreads();
    for (int l = w; l < Lz; l += 8) {
        float p = 0.f;
        const float* xr = xb + (size_t)l*Dz;
        for (int k = lane; k < Dz; k += 32) p += q[k]*xr[k];
        p = warpSum(p);
        if (lane == 0) sc[l] = (l < len) ? p : -60000.0f;
    }
    __syncthreads();
    float m1 = fmaxf(sc[tid], sc[tid + 256]);
    m1 = warpMax(m1);
    if (lane == 0) red[w] = m1;
    __syncthreads();
    float mx = -3.4e38f;
#pragma unroll
    for (int i = 0; i < 8; i++) mx = fmaxf(mx, red[i]);
    __syncthreads();
    float e0 = __expf(sc[tid] - mx), e1 = __expf(sc[tid + 256] - mx);
    sc[tid] = e0; sc[tid + 256] = e1;
    float s = blkSum256(e0 + e1, red);
    float inv = 1.0f / s;
    float acc = 0.f;
    for (int l = 0; l < Lz; l++) acc += sc[l] * xb[(size_t)l*Dz + tid];
    g_z[b*Dz + tid] = acc * inv;
}

// -------- host orchestration --------
extern "C" void kernel_launch(void* const* d_in, const int* in_sizes, int n_in,
                              void* d_out, int out_size)
{
    (void)in_sizes; (void)n_in; (void)out_size;
    const int*   tokens  = (const int*)  d_in[0];
    // d_in[1] = mask (unused; derived from tokens)
    const float* tok_emb = (const float*)d_in[2];
    const float* pos_emb = (const float*)d_in[3];
    const float* eg      = (const float*)d_in[4];
    const float* ebt     = (const float*)d_in[5];
    const float* ln1g    = (const float*)d_in[6];
    const float* ln1b    = (const float*)d_in[7];
    const float* Wqkv    = (const float*)d_in[8];
    const float* bqkv    = (const float*)d_in[9];
    const float* Wo      = (const float*)d_in[10];
    const float* bo      = (const float*)d_in[11];
    const float* ln2g    = (const float*)d_in[12];
    const float* ln2b    = (const float*)d_in[13];
    const float* W1      = (const float*)d_in[14];
    const float* b1      = (const float*)d_in[15];
    const float* W2      = (const float*)d_in[16];
    const float* b2      = (const float*)d_in[17];
    // d_in[18..21] = GRU params: dead code (m never affects output) — skipped
    const float* clsW    = (const float*)d_in[22];
    const float* clsb    = (const float*)d_in[23];
    float* out = (float*)d_out;

    float *px, *ph, *pqkv, *po, *pffn, *pz;
    cudaGetSymbolAddress((void**)&px,   g_x);
    cudaGetSymbolAddress((void**)&ph,   g_h);
    cudaGetSymbolAddress((void**)&pqkv, g_qkv);
    cudaGetSymbolAddress((void**)&po,   g_o);
    cudaGetSymbolAddress((void**)&pffn, g_ffn);
    cudaGetSymbolAddress((void**)&pz,   g_z);

    cudaFuncSetAttribute(attn2_kernel,
        cudaFuncAttributeMaxDynamicSharedMemorySize, ATTN2_SMEM);

    const int M = Bz * Lz;   // 32768

    lengths_kernel<<<Bz, 256>>>(tokens);
    embed_kernel<<<M, 256>>>(tokens, tok_emb, pos_emb, eg, ebt);

    for (int e = 0; e < Kz; e++) {
        ln_kernel<<<M, 256>>>(px, ln1g + e*Dz, ln1b + e*Dz, ph);
        gemm_nt2<false,false><<<dim3(3*Dz/128, M/128), 256>>>(
            ph, Wqkv + (size_t)e*3*Dz*Dz, bqkv + (size_t)e*3*Dz, nullptr,
            pqkv, M, 3*Dz, Dz);
        attn2_kernel<<<dim3(Lz/64, Hz, Bz), 256, ATTN2_SMEM>>>(pqkv, po);
        gemm_nt2<false,true><<<dim3(Dz/128, M/128), 256>>>(
            po, Wo + (size_t)e*Dz*Dz, bo + (size_t)e*Dz, px,
            px, M, Dz, Dz);
        ln_kernel<<<M, 256>>>(px, ln2g + e*Dz, ln2b + e*Dz, ph);
        gemm_nt2<true,false><<<dim3(FFNz/128, M/128), 256>>>(
            ph, W1 + (size_t)e*FFNz*Dz, b1 + (size_t)e*FFNz, nullptr,
            pffn, M, FFNz, Dz);
        gemm_nt2<false,true><<<dim3(Dz/128, M/128), 256>>>(
            pffn, W2 + (size_t)e*Dz*FFNz, b2 + (size_t)e*Dz, px,
            px, M, Dz, FFNz);
    }

    pool_kernel<<<Bz, 256>>>(px);
    gemm_nt<false,false><<<dim3(Vz/128, Bz/64), 256>>>(
        pz, clsW, clsb, nullptr, out, Bz, Vz, Dz);
}